// round 15
// baseline (speedup 1.0000x reference)
#include <cuda_runtime.h>
#include <math.h>
#include <stdint.h>

// Problem constants
#define Bv   2
#define Sv   2048
#define Hv   2048
#define NHv  16
#define HDv  128
#define Iv   5632
#define Tv   (Bv * Sv)            // 4096 tokens
#define EPSv 1e-5f
#define SCALEv 0.08838834764831845f   // 1/sqrt(128)

// Smem strides (words). 136 ≡ 8, 20 ≡ 20 (mod 32): fragment-read bank
// indices are bijections over the 32 lanes -> conflict-free.
#define STRIDE_KN 136    // [k][n] layout rows (B, non-transposed)
#define STRIDE_MK 20     // [m][k] layout rows (A, and B when TRANSB)
#define A_BUF 5120       // 256 rows * 20 words
#define B_BUF 2560       // max(16*136=2176, 128*20=2560)
#define SMEM_BYTES ((2 * A_BUF + 2 * B_BUF) * 4)   // 61440

// ---------------- scratch (static __device__: allocation-free) -------------
__device__ float g_xn[Tv * Hv];
__device__ float g_q[Tv * Hv];
__device__ float g_k[Tv * Hv];
__device__ float g_v[Tv * Hv];
__device__ float g_scores[(size_t)Bv * NHv * Sv * Sv];  // 536 MB
__device__ float g_ctx[Tv * Hv];
__device__ float g_hidden[Tv * Hv];
__device__ float g_y[Tv * Hv];
__device__ float g_fc1[Tv * 2 * Iv];
__device__ float g_act[Tv * Iv];
// tf32-pre-rounded weights
__device__ float g_qw[Hv * Hv];
__device__ float g_kw[Hv * Hv];
__device__ float g_vw[Hv * Hv];
__device__ float g_ow[Hv * Hv];
__device__ float g_fc1w[Hv * 2 * Iv];
__device__ float g_fc2w[Iv * Hv];

// ---------------- tf32 helpers --------------------------------------------
__device__ __forceinline__ float tf32r(float x) {
    uint32_t u;
    asm("cvt.rna.tf32.f32 %0, %1;" : "=r"(u) : "f"(x));
    return __uint_as_float(u);
}

__device__ __forceinline__ void mma_tf32(float* d, const uint32_t* a, const uint32_t* b) {
    asm volatile(
        "mma.sync.aligned.m16n8k8.row.col.f32.tf32.tf32.f32 "
        "{%0,%1,%2,%3}, {%4,%5,%6,%7}, {%8,%9}, {%0,%1,%2,%3};\n"
        : "+f"(d[0]), "+f"(d[1]), "+f"(d[2]), "+f"(d[3])
        : "r"(a[0]), "r"(a[1]), "r"(a[2]), "r"(a[3]), "r"(b[0]), "r"(b[1]));
}

#define CP_ASYNC16(dst_u32, src_ptr) \
    asm volatile("cp.async.cg.shared.global [%0], [%1], 16;" :: "r"(dst_u32), "l"(src_ptr))
#define CP_COMMIT() asm volatile("cp.async.commit_group;" ::: "memory")
#define CP_WAIT0()  asm volatile("cp.async.wait_group 0;" ::: "memory")

// ---------------- weight pre-rounding: out[i] = tf32(in[i]) ---------------
__global__ void cvt_tf32_kernel(const float* __restrict__ in,
                                float* __restrict__ out, int n4) {
    int i = blockIdx.x * blockDim.x + threadIdx.x;
    if (i >= n4) return;
    float4 v = ((const float4*)in)[i];
    v.x = tf32r(v.x); v.y = tf32r(v.y); v.z = tf32r(v.z); v.w = tf32r(v.w);
    ((float4*)out)[i] = v;
}

// ---------------- RMSNorm: one block per row; output tf32-rounded ---------
__global__ void rmsnorm_kernel(const float* __restrict__ x,
                               const float* __restrict__ w,
                               float* __restrict__ out) {
    int r = blockIdx.x;
    const float* xr = x + (size_t)r * Hv;
    float* orow = out + (size_t)r * Hv;
    float v[8];
    float ss = 0.f;
#pragma unroll
    for (int i = 0; i < 8; i++) {
        v[i] = xr[threadIdx.x + i * 256];
        ss += v[i] * v[i];
    }
    __shared__ float red[32];
    int lane = threadIdx.x & 31, wid = threadIdx.x >> 5;
#pragma unroll
    for (int o = 16; o > 0; o >>= 1) ss += __shfl_xor_sync(0xffffffffu, ss, o);
    if (lane == 0) red[wid] = ss;
    __syncthreads();
    if (wid == 0) {
        float t = (lane < 8) ? red[lane] : 0.f;
#pragma unroll
        for (int o = 4; o > 0; o >>= 1) t += __shfl_xor_sync(0xffffffffu, t, o);
        if (lane == 0) red[0] = rsqrtf(t * (1.0f / Hv) + EPSv);
    }
    __syncthreads();
    float rs = red[0];
#pragma unroll
    for (int i = 0; i < 8; i++) {
        int c = threadIdx.x + i * 256;
        orow[c] = tf32r(v[i] * rs * w[c]);
    }
}

// ---------------- Softmax (mask+scale); output tf32-rounded ---------------
__global__ void softmax_kernel(float* __restrict__ sc,
                               const float* __restrict__ mask) {
    int r = blockIdx.x;
    int b = r / (NHv * Sv);
    float* row = sc + (size_t)r * Sv;
    const float* mrow = mask + (size_t)b * Sv;

    float l[8];
    float mx = -1e30f;
#pragma unroll
    for (int i = 0; i < 8; i++) {
        int c = threadIdx.x + i * 256;
        float val = row[c] * SCALEv + (1.0f - mrow[c]) * -10000.0f;
        l[i] = val;
        mx = fmaxf(mx, val);
    }
    __shared__ float red[32];
    int lane = threadIdx.x & 31, wid = threadIdx.x >> 5;
#pragma unroll
    for (int o = 16; o > 0; o >>= 1) mx = fmaxf(mx, __shfl_xor_sync(0xffffffffu, mx, o));
    if (lane == 0) red[wid] = mx;
    __syncthreads();
    if (wid == 0) {
        float t = (lane < 8) ? red[lane] : -1e30f;
#pragma unroll
        for (int o = 4; o > 0; o >>= 1) t = fmaxf(t, __shfl_xor_sync(0xffffffffu, t, o));
        if (lane == 0) red[0] = t;
    }
    __syncthreads();
    mx = red[0];
    __syncthreads();

    float sum = 0.f;
#pragma unroll
    for (int i = 0; i < 8; i++) {
        float e = __expf(l[i] - mx);
        l[i] = e;
        sum += e;
    }
#pragma unroll
    for (int o = 16; o > 0; o >>= 1) sum += __shfl_xor_sync(0xffffffffu, sum, o);
    if (lane == 0) red[wid] = sum;
    __syncthreads();
    if (wid == 0) {
        float t = (lane < 8) ? red[lane] : 0.f;
#pragma unroll
        for (int o = 4; o > 0; o >>= 1) t += __shfl_xor_sync(0xffffffffu, t, o);
        if (lane == 0) red[0] = t;
    }
    __syncthreads();
    float inv = 1.0f / red[0];
#pragma unroll
    for (int i = 0; i < 8; i++) {
        int c = threadIdx.x + i * 256;
        row[c] = tf32r(l[i] * inv);
    }
}

// ---------------- SwiGLU; output tf32-rounded -----------------------------
__global__ void swiglu_kernel(const float* __restrict__ h,
                              float* __restrict__ act) {
    int idx = blockIdx.x * blockDim.x + threadIdx.x;
    int total4 = Tv * Iv / 4;
    if (idx >= total4) return;
    int per_row4 = Iv / 4;
    int t = idx / per_row4, j4 = idx - t * per_row4;
    const float4* grow = (const float4*)(h + (size_t)t * (2 * Iv));
    float4 g = grow[j4];
    float4 u = grow[j4 + per_row4];
    float4 r;
    r.x = tf32r((g.x / (1.0f + __expf(-g.x))) * u.x);
    r.y = tf32r((g.y / (1.0f + __expf(-g.y))) * u.y);
    r.z = tf32r((g.z / (1.0f + __expf(-g.z))) * u.z);
    r.w = tf32r((g.w / (1.0f + __expf(-g.w))) * u.w);
    ((float4*)act)[idx] = r;
}

// ---------------- tf32 tensor-core GEMM (cp.async, 256x128 CTA tile) ------
// Inputs MUST be tf32-pre-rounded. BM=256, BN=128, BK=16, 256 threads,
// 8 warps as 4(M)x2(N), warp tile 64x64 -> 1.37 smem wavefronts/MMA.
// A staged [m][k] stride 20; B: TRANSB -> [n][k] stride 20, else [k][n] 136.
// Dynamic smem (61.4 KB), double-buffered, one sync per k-slab.
// Requirements: M%256==0, N%128==0, K%16==0. Batched via blockIdx.z.
template <bool TRANSB>
__global__ __launch_bounds__(256)
void tgemm_kernel(const float* __restrict__ A, const float* __restrict__ Bm,
                  const float* __restrict__ bias, const float* __restrict__ resid,
                  float* __restrict__ C,
                  int M, int N, int K, int lda, int ldb, int ldc,
                  int bInner, int roundC,
                  long aIn, long aOut, long bIn, long bOut, long cIn, long cOut) {
    int z = blockIdx.z;
    int zi = z % bInner, zo = z / bInner;
    A += (long)zi * aIn + (long)zo * aOut;
    Bm += (long)zi * bIn + (long)zo * bOut;
    long coff = (long)zi * cIn + (long)zo * cOut;
    C += coff;
    if (resid) resid += coff;

    extern __shared__ uint32_t dynsmem[];
    uint32_t* Abase = dynsmem;                 // 2 * A_BUF
    uint32_t* Bbase = dynsmem + 2 * A_BUF;     // 2 * B_BUF

    int tid = threadIdx.x;
    int lane = tid & 31;
    int warp = tid >> 5;
    int g = lane >> 2;        // 0..7
    int tg = lane & 3;        // 0..3
    int warp_m = warp >> 1;   // 4 warps along M (64 each)
    int warp_n = warp & 1;    // 2 warps along N (64 each)
    int m0 = blockIdx.y * 256, n0 = blockIdx.x * 128;

    uint32_t sA = (uint32_t)__cvta_generic_to_shared(Abase);
    uint32_t sB = (uint32_t)__cvta_generic_to_shared(Bbase);

    // A staging: one row per thread (256 rows), 4 x 16B per slab
    const float* Ap = A + (long)(m0 + tid) * lda;
    uint32_t aDst = (uint32_t)(tid * STRIDE_MK) * 4u;

    // B staging
    const float* Bp;
    uint32_t bDst0, bDst1;
    long bStep;
    if (TRANSB) {             // B[N,K]: row = n, into [n][k]@20
        int bN = tid >> 1;
        int bC = (tid & 1) * 8;
        Bp = Bm + (long)(n0 + bN) * ldb + bC;
        bDst0 = (uint32_t)(bN * STRIDE_MK + bC) * 4u;
        bDst1 = bDst0 + 16u;
        bStep = 16;
    } else {                  // B[K,N]: row = k, into [k][n]@136
        int bR = tid >> 4;    // 0..15
        int bC = (tid & 15) * 8;
        Bp = Bm + (long)bR * ldb + n0 + bC;
        bDst0 = (uint32_t)(bR * STRIDE_KN + bC) * 4u;
        bDst1 = bDst0 + 16u;
        bStep = (long)16 * ldb;
    }

    float acc[4][8][4];
#pragma unroll
    for (int i = 0; i < 4; i++)
#pragma unroll
        for (int j = 0; j < 8; j++)
#pragma unroll
            for (int r = 0; r < 4; r++) acc[i][j][r] = 0.f;

    // ---- stage slab 0 into buffer 0 ----
    CP_ASYNC16(sA + aDst,       Ap);
    CP_ASYNC16(sA + aDst + 16u, Ap + 4);
    CP_ASYNC16(sA + aDst + 32u, Ap + 8);
    CP_ASYNC16(sA + aDst + 48u, Ap + 12);
    CP_ASYNC16(sB + bDst0, Bp);
    CP_ASYNC16(sB + bDst1, Bp + 4);
    CP_COMMIT();
    CP_WAIT0();
    __syncthreads();

    const float* ApNext = Ap + 16;
    const float* BpNext = Bp + bStep;
    int buf = 0;

    for (int kt = 0; kt < K; kt += 16) {
        bool has_next = (kt + 16 < K);
        if (has_next) {
            uint32_t offA = (buf ^ 1) ? (uint32_t)(A_BUF * 4) : 0u;
            uint32_t offB = (buf ^ 1) ? (uint32_t)(B_BUF * 4) : 0u;
            CP_ASYNC16(sA + offA + aDst,       ApNext);
            CP_ASYNC16(sA + offA + aDst + 16u, ApNext + 4);
            CP_ASYNC16(sA + offA + aDst + 32u, ApNext + 8);
            CP_ASYNC16(sA + offA + aDst + 48u, ApNext + 12);
            CP_ASYNC16(sB + offB + bDst0, BpNext);
            CP_ASYNC16(sB + offB + bDst1, BpNext + 4);
            CP_COMMIT();
            ApNext += 16;
            BpNext += bStep;
        }

        const uint32_t* Ab = Abase + buf * A_BUF;
        const uint32_t* Bb = Bbase + buf * B_BUF;
#pragma unroll
        for (int kk = 0; kk < 16; kk += 8) {
            uint32_t af[4][4], bf[8][2];
#pragma unroll
            for (int im = 0; im < 4; im++) {
                int rowb = warp_m * 64 + im * 16 + g;
                af[im][0] = Ab[rowb * STRIDE_MK + kk + tg];
                af[im][1] = Ab[(rowb + 8) * STRIDE_MK + kk + tg];
                af[im][2] = Ab[rowb * STRIDE_MK + kk + tg + 4];
                af[im][3] = Ab[(rowb + 8) * STRIDE_MK + kk + tg + 4];
            }
#pragma unroll
            for (int jn = 0; jn < 8; jn++) {
                int colb = warp_n * 64 + jn * 8 + g;
                if (TRANSB) {
                    bf[jn][0] = Bb[colb * STRIDE_MK + kk + tg];
                    bf[jn][1] = Bb[colb * STRIDE_MK + kk + tg + 4];
                } else {
                    bf[jn][0] = Bb[(kk + tg) * STRIDE_KN + colb];
                    bf[jn][1] = Bb[(kk + tg + 4) * STRIDE_KN + colb];
                }
            }
#pragma unroll
            for (int im = 0; im < 4; im++)
#pragma unroll
                for (int jn = 0; jn < 8; jn++)
                    mma_tf32(acc[im][jn], af[im], bf[jn]);
        }

        if (has_next) {
            CP_WAIT0();
            __syncthreads();
            buf ^= 1;
        }
    }

    // Epilogue
#pragma unroll
    for (int im = 0; im < 4; im++) {
#pragma unroll
        for (int jn = 0; jn < 8; jn++) {
            int r0 = m0 + warp_m * 64 + im * 16 + g;
            int c0 = n0 + warp_n * 64 + jn * 8 + tg * 2;
            float2 bb = make_float2(0.f, 0.f);
            if (bias) bb = *(const float2*)(bias + c0);
            float2 o0 = make_float2(acc[im][jn][0] + bb.x, acc[im][jn][1] + bb.y);
            float2 o1 = make_float2(acc[im][jn][2] + bb.x, acc[im][jn][3] + bb.y);
            if (resid) {
                float2 rr0 = *(const float2*)(resid + (long)r0 * ldc + c0);
                float2 rr1 = *(const float2*)(resid + (long)(r0 + 8) * ldc + c0);
                o0.x += rr0.x; o0.y += rr0.y;
                o1.x += rr1.x; o1.y += rr1.y;
            }
            if (roundC) {
                o0.x = tf32r(o0.x); o0.y = tf32r(o0.y);
                o1.x = tf32r(o1.x); o1.y = tf32r(o1.y);
            }
            *(float2*)(C + (long)r0 * ldc + c0) = o0;
            *(float2*)(C + (long)(r0 + 8) * ldc + c0) = o1;
        }
    }
}

// ---------------- launcher -------------------------------------------------
extern "C" void kernel_launch(void* const* d_in, const int* in_sizes, int n_in,
                              void* d_out, int out_size) {
    (void)in_sizes; (void)n_in; (void)out_size;
    const float* hs        = (const float*)d_in[0];
    const float* mask      = (const float*)d_in[1];
    const float* q_w       = (const float*)d_in[2];
    const float* q_b       = (const float*)d_in[3];
    const float* k_w       = (const float*)d_in[4];
    const float* k_b       = (const float*)d_in[5];
    const float* v_w       = (const float*)d_in[6];
    const float* v_b       = (const float*)d_in[7];
    const float* o_w       = (const float*)d_in[8];
    const float* o_b       = (const float*)d_in[9];
    const float* fc1_w     = (const float*)d_in[10];
    const float* fc1_b     = (const float*)d_in[11];
    const float* fc2_w     = (const float*)d_in[12];
    const float* fc2_b     = (const float*)d_in[13];
    const float* in_norm_w = (const float*)d_in[14];
    const float* post_norm_w = (const float*)d_in[15];
    float* out = (float*)d_out;

    float *xn, *q, *k, *v, *sc, *ctx, *hid, *y, *fc1, *act;
    float *qw, *kw, *vw, *ow, *fc1w, *fc2w;
    cudaGetSymbolAddress((void**)&xn,  g_xn);
    cudaGetSymbolAddress((void**)&q,   g_q);
    cudaGetSymbolAddress((void**)&k,   g_k);
    cudaGetSymbolAddress((void**)&v,   g_v);
    cudaGetSymbolAddress((void**)&sc,  g_scores);
    cudaGetSymbolAddress((void**)&ctx, g_ctx);
    cudaGetSymbolAddress((void**)&hid, g_hidden);
    cudaGetSymbolAddress((void**)&y,   g_y);
    cudaGetSymbolAddress((void**)&fc1, g_fc1);
    cudaGetSymbolAddress((void**)&act, g_act);
    cudaGetSymbolAddress((void**)&qw,  g_qw);
    cudaGetSymbolAddress((void**)&kw,  g_kw);
    cudaGetSymbolAddress((void**)&vw,  g_vw);
    cudaGetSymbolAddress((void**)&ow,  g_ow);
    cudaGetSymbolAddress((void**)&fc1w, g_fc1w);
    cudaGetSymbolAddress((void**)&fc2w, g_fc2w);

    // raise dynamic smem limit for both instantiations (host-side, idempotent)
    cudaFuncSetAttribute(tgemm_kernel<false>,
                         cudaFuncAttributeMaxDynamicSharedMemorySize, SMEM_BYTES);
    cudaFuncSetAttribute(tgemm_kernel<true>,
                         cudaFuncAttributeMaxDynamicSharedMemorySize, SMEM_BYTES);

    // 0. pre-round weights to tf32
    int nW = Hv * Hv / 4;
    cvt_tf32_kernel<<<(nW + 255) / 256, 256>>>(q_w, qw, nW);
    cvt_tf32_kernel<<<(nW + 255) / 256, 256>>>(k_w, kw, nW);
    cvt_tf32_kernel<<<(nW + 255) / 256, 256>>>(v_w, vw, nW);
    cvt_tf32_kernel<<<(nW + 255) / 256, 256>>>(o_w, ow, nW);
    int nF1 = Hv * 2 * Iv / 4;
    cvt_tf32_kernel<<<(nF1 + 255) / 256, 256>>>(fc1_w, fc1w, nF1);
    int nF2 = Iv * Hv / 4;
    cvt_tf32_kernel<<<(nF2 + 255) / 256, 256>>>(fc2_w, fc2w, nF2);

    // 1. input RMSNorm (rounded)
    rmsnorm_kernel<<<Tv, 256>>>(hs, in_norm_w, xn);

    // 2. Q/K/V projections (outputs rounded: feed scores/ctx GEMMs)
    dim3 gProj(Hv / 128, Tv / 256, 1);
    tgemm_kernel<false><<<gProj, 256, SMEM_BYTES>>>(xn, qw, q_b, nullptr, q,
        Tv, Hv, Hv, Hv, Hv, Hv, 1, 1, 0, 0, 0, 0, 0, 0);
    tgemm_kernel<false><<<gProj, 256, SMEM_BYTES>>>(xn, kw, k_b, nullptr, k,
        Tv, Hv, Hv, Hv, Hv, Hv, 1, 1, 0, 0, 0, 0, 0, 0);
    tgemm_kernel<false><<<gProj, 256, SMEM_BYTES>>>(xn, vw, v_b, nullptr, v,
        Tv, Hv, Hv, Hv, Hv, Hv, 1, 1, 0, 0, 0, 0, 0, 0);

    // 3. scores = Q @ K^T (batched over 32 heads); softmax rounds after
    dim3 gSc(Sv / 128, Sv / 256, Bv * NHv);
    tgemm_kernel<true><<<gSc, 256, SMEM_BYTES>>>(q, k, nullptr, nullptr, sc,
        Sv, Sv, HDv, Hv, Hv, Sv, NHv, 0,
        HDv, (long)Sv * Hv, HDv, (long)Sv * Hv,
        (long)Sv * Sv, (long)NHv * Sv * Sv);

    // 4. softmax (rounded output)
    softmax_kernel<<<Bv * NHv * Sv, 256>>>(sc, mask);

    // 5. ctx = P @ V (rounded: feeds O-proj)
    dim3 gCtx(HDv / 128, Sv / 256, Bv * NHv);
    tgemm_kernel<false><<<gCtx, 256, SMEM_BYTES>>>(sc, v, nullptr, nullptr, ctx,
        Sv, HDv, Sv, Sv, Hv, Hv, NHv, 1,
        (long)Sv * Sv, (long)NHv * Sv * Sv,
        HDv, (long)Sv * Hv, HDv, (long)Sv * Hv);

    // 6. O projection + residual -> hidden (NOT rounded: residual path)
    tgemm_kernel<false><<<gProj, 256, SMEM_BYTES>>>(ctx, ow, o_b, hs, hid,
        Tv, Hv, Hv, Hv, Hv, Hv, 1, 0, 0, 0, 0, 0, 0, 0);

    // 7. post RMSNorm (rounded)
    rmsnorm_kernel<<<Tv, 256>>>(hid, post_norm_w, y);

    // 8. FC1 (swiglu rounds after)
    dim3 gFc1((2 * Iv) / 128, Tv / 256, 1);
    tgemm_kernel<false><<<gFc1, 256, SMEM_BYTES>>>(y, fc1w, fc1_b, nullptr, fc1,
        Tv, 2 * Iv, Hv, Hv, 2 * Iv, 2 * Iv, 1, 0, 0, 0, 0, 0, 0, 0);

    // 9. SwiGLU (rounded)
    swiglu_kernel<<<(Tv * Iv / 4 + 255) / 256, 256>>>(fc1, act);

    // 10. FC2 + residual -> out (NOT rounded: final output)
    tgemm_kernel<false><<<gProj, 256, SMEM_BYTES>>>(act, fc2w, fc2_b, hid, out,
        Tv, Hv, Iv, Iv, Hv, Hv, 1, 0, 0, 0, 0, 0, 0, 0);
}

// round 16
// speedup vs baseline: 2.0133x; 2.0133x over previous
#include <cuda_runtime.h>
#include <cuda_fp16.h>
#include <math.h>
#include <stdint.h>

// Problem constants
#define Bv   2
#define Sv   2048
#define Hv   2048
#define NHv  16
#define HDv  128
#define Iv   5632
#define Tv   (Bv * Sv)            // 4096 tokens
#define EPSv 1e-5f
#define SCALEv 0.08838834764831845f   // 1/sqrt(128)

// Smem geometry: per k-slab of 32 halves, each row holds 16 data words.
// Row stride 20 words (20 mod 32): fragment-read bank = (20g + tg) mod 32
// is a bijection over the warp -> conflict-free (same math as benched R14).
#define STRIDE_W 20
#define BUF_WORDS (128 * STRIDE_W)   // 2560 words = 10 KB per buffer

// ---------------- scratch (static __device__: allocation-free) -------------
__device__ float  g_scores[(size_t)Bv * NHv * Sv * Sv];  // 536 MB fp32
__device__ float  g_hidden[Tv * Hv];
__device__ __half g_xnh[Tv * Hv];
__device__ __half g_qh[Tv * Hv];
__device__ __half g_kh[Tv * Hv];
__device__ __half g_vh[Tv * Hv];
__device__ __half g_vt[Tv * Hv];          // per-head transposed V [bh][hd][s]
__device__ __half g_p[(size_t)Bv * NHv * Sv * Sv];   // 268 MB fp16 probs
__device__ __half g_ctxh[Tv * Hv];
__device__ __half g_yh[Tv * Hv];
__device__ __half g_fc1h[(size_t)Tv * 2 * Iv];
__device__ __half g_acth[(size_t)Tv * Iv];
// fp16 transposed weights [N][K]
__device__ __half g_qwT[Hv * Hv];
__device__ __half g_kwT[Hv * Hv];
__device__ __half g_vwT[Hv * Hv];
__device__ __half g_owT[Hv * Hv];
__device__ __half g_fc1wT[(size_t)2 * Iv * Hv];
__device__ __half g_fc2wT[(size_t)Hv * Iv];

// ---------------- mma + cp.async helpers ----------------------------------
__device__ __forceinline__ void mma_f16(float* d, const uint32_t* a, const uint32_t* b) {
    asm volatile(
        "mma.sync.aligned.m16n8k16.row.col.f32.f16.f16.f32 "
        "{%0,%1,%2,%3}, {%4,%5,%6,%7}, {%8,%9}, {%0,%1,%2,%3};\n"
        : "+f"(d[0]), "+f"(d[1]), "+f"(d[2]), "+f"(d[3])
        : "r"(a[0]), "r"(a[1]), "r"(a[2]), "r"(a[3]), "r"(b[0]), "r"(b[1]));
}

#define CP_ASYNC16(dst_u32, src_ptr) \
    asm volatile("cp.async.cg.shared.global [%0], [%1], 16;" :: "r"(dst_u32), "l"(src_ptr))
#define CP_COMMIT() asm volatile("cp.async.commit_group;" ::: "memory")
#define CP_WAIT0()  asm volatile("cp.async.wait_group 0;" ::: "memory")

// ---------------- weight transpose+cvt: fp32 [K][N] -> fp16 [N][K] --------
__global__ void wt_kernel(const float* __restrict__ in, __half* __restrict__ out,
                          int K, int N) {
    __shared__ __half tile[32][33];
    int nb = blockIdx.x * 32, kb = blockIdx.y * 32;
    int tx = threadIdx.x, ty = threadIdx.y;   // 32 x 8
#pragma unroll
    for (int i = 0; i < 4; i++) {
        int r = ty + 8 * i;
        tile[r][tx] = __float2half_rn(in[(size_t)(kb + r) * N + nb + tx]);
    }
    __syncthreads();
#pragma unroll
    for (int i = 0; i < 4; i++) {
        int r = ty + 8 * i;
        out[(size_t)(nb + r) * K + kb + tx] = tile[tx][r];
    }
}

// ---------------- V transpose: [b,s,h,d] fp16 -> [bh][d][s] fp16 ----------
__global__ void vtr_kernel(const __half* __restrict__ vh, __half* __restrict__ vt) {
    __shared__ __half tile[32][33];
    int z = blockIdx.z;                       // b*NH + h
    int b = z / NHv, h = z % NHv;
    int sb = blockIdx.x * 32, db = blockIdx.y * 32;
    int tx = threadIdx.x, ty = threadIdx.y;
#pragma unroll
    for (int i = 0; i < 4; i++) {
        int r = ty + 8 * i;
        tile[r][tx] = vh[(size_t)(b * Sv + sb + r) * Hv + h * HDv + db + tx];
    }
    __syncthreads();
#pragma unroll
    for (int i = 0; i < 4; i++) {
        int r = ty + 8 * i;
        vt[((size_t)z * HDv + db + r) * Sv + sb + tx] = tile[tx][r];
    }
}

// ---------------- RMSNorm: fp32 in -> fp16 out ----------------------------
__global__ void rmsnorm_kernel(const float* __restrict__ x,
                               const float* __restrict__ w,
                               __half* __restrict__ out) {
    int r = blockIdx.x;
    const float* xr = x + (size_t)r * Hv;
    __half* orow = out + (size_t)r * Hv;
    float v[8];
    float ss = 0.f;
#pragma unroll
    for (int i = 0; i < 8; i++) {
        v[i] = xr[threadIdx.x + i * 256];
        ss += v[i] * v[i];
    }
    __shared__ float red[32];
    int lane = threadIdx.x & 31, wid = threadIdx.x >> 5;
#pragma unroll
    for (int o = 16; o > 0; o >>= 1) ss += __shfl_xor_sync(0xffffffffu, ss, o);
    if (lane == 0) red[wid] = ss;
    __syncthreads();
    if (wid == 0) {
        float t = (lane < 8) ? red[lane] : 0.f;
#pragma unroll
        for (int o = 4; o > 0; o >>= 1) t += __shfl_xor_sync(0xffffffffu, t, o);
        if (lane == 0) red[0] = rsqrtf(t * (1.0f / Hv) + EPSv);
    }
    __syncthreads();
    float rs = red[0];
#pragma unroll
    for (int i = 0; i < 8; i++) {
        int c = threadIdx.x + i * 256;
        orow[c] = __float2half_rn(v[i] * rs * w[c]);
    }
}

// ---------------- Softmax: fp32 scores -> fp16 probs ----------------------
__global__ void softmax_kernel(const float* __restrict__ sc,
                               const float* __restrict__ mask,
                               __half* __restrict__ p) {
    int r = blockIdx.x;
    int b = r / (NHv * Sv);
    const float* row = sc + (size_t)r * Sv;
    __half* prow = p + (size_t)r * Sv;
    const float* mrow = mask + (size_t)b * Sv;

    float l[8];
    float mx = -1e30f;
#pragma unroll
    for (int i = 0; i < 8; i++) {
        int c = threadIdx.x + i * 256;
        float val = row[c] * SCALEv + (1.0f - mrow[c]) * -10000.0f;
        l[i] = val;
        mx = fmaxf(mx, val);
    }
    __shared__ float red[32];
    int lane = threadIdx.x & 31, wid = threadIdx.x >> 5;
#pragma unroll
    for (int o = 16; o > 0; o >>= 1) mx = fmaxf(mx, __shfl_xor_sync(0xffffffffu, mx, o));
    if (lane == 0) red[wid] = mx;
    __syncthreads();
    if (wid == 0) {
        float t = (lane < 8) ? red[lane] : -1e30f;
#pragma unroll
        for (int o = 4; o > 0; o >>= 1) t = fmaxf(t, __shfl_xor_sync(0xffffffffu, t, o));
        if (lane == 0) red[0] = t;
    }
    __syncthreads();
    mx = red[0];
    __syncthreads();

    float sum = 0.f;
#pragma unroll
    for (int i = 0; i < 8; i++) {
        float e = __expf(l[i] - mx);
        l[i] = e;
        sum += e;
    }
#pragma unroll
    for (int o = 16; o > 0; o >>= 1) sum += __shfl_xor_sync(0xffffffffu, sum, o);
    if (lane == 0) red[wid] = sum;
    __syncthreads();
    if (wid == 0) {
        float t = (lane < 8) ? red[lane] : 0.f;
#pragma unroll
        for (int o = 4; o > 0; o >>= 1) t += __shfl_xor_sync(0xffffffffu, t, o);
        if (lane == 0) red[0] = t;
    }
    __syncthreads();
    float inv = 1.0f / red[0];
#pragma unroll
    for (int i = 0; i < 8; i++) {
        int c = threadIdx.x + i * 256;
        prow[c] = __float2half_rn(l[i] * inv);
    }
}

// ---------------- SwiGLU: fp16 in/out, fp32 math --------------------------
__global__ void swiglu_kernel(const __half* __restrict__ h,
                              __half* __restrict__ act) {
    int idx = blockIdx.x * blockDim.x + threadIdx.x;   // 8-half units
    int total8 = Tv * Iv / 8;
    if (idx >= total8) return;
    int per8 = Iv / 8;
    int t = idx / per8, j = idx - t * per8;
    const __half* base = h + (size_t)t * (2 * Iv) + j * 8;
    uint4 gv = *(const uint4*)(base);
    uint4 uv = *(const uint4*)(base + Iv);
    const __half2* g2 = (const __half2*)&gv;
    const __half2* u2 = (const __half2*)&uv;
    uint4 ov;
    __half2* o2 = (__half2*)&ov;
#pragma unroll
    for (int i = 0; i < 4; i++) {
        float2 gf = __half22float2(g2[i]);
        float2 uf = __half22float2(u2[i]);
        float r0 = (gf.x / (1.0f + __expf(-gf.x))) * uf.x;
        float r1 = (gf.y / (1.0f + __expf(-gf.y))) * uf.y;
        o2[i] = __floats2half2_rn(r0, r1);
    }
    *(uint4*)(act + (size_t)t * Iv + j * 8) = ov;
}

// ---------------- fp16 tensor-core GEMM: C = A @ B^T [+bias] [+resid] -----
// A [M,K]h row-major (lda), B [N,K]h row-major (ldb) -> C[M,N] = A·Bᵀ.
// BM=BN=128, BK=32 halves, 256 threads, 8 warps (2M x 4N), warp tile 64x32,
// m16n8k16. Both operands staged [row][k] stride 20 words via direct 16B
// cp.async, double-buffered, one sync per slab. M,N %128==0, K%32==0.
// OUTH: write fp16 C; else fp32 C (+optional fp32 resid).
template <bool OUTH>
__global__ __launch_bounds__(256, 2)
void hgemm_kernel(const __half* __restrict__ A, const __half* __restrict__ Bm,
                  const float* __restrict__ bias, const float* __restrict__ resid,
                  void* __restrict__ Cv,
                  int M, int N, int K, int lda, int ldb, int ldc,
                  int bInner,
                  long aIn, long aOut, long bIn, long bOut, long cIn, long cOut) {
    int z = blockIdx.z;
    int zi = z % bInner, zo = z / bInner;
    A += (long)zi * aIn + (long)zo * aOut;
    Bm += (long)zi * bIn + (long)zo * bOut;
    long coff = (long)zi * cIn + (long)zo * cOut;

    __shared__ uint32_t AsF[2 * BUF_WORDS];
    __shared__ uint32_t BsF[2 * BUF_WORDS];

    int tid = threadIdx.x;
    int lane = tid & 31;
    int warp = tid >> 5;
    int g = lane >> 2;        // 0..7
    int tg = lane & 3;        // 0..3
    int warp_m = warp & 1;    // 2 warps along M (64 each)
    int warp_n = warp >> 1;   // 4 warps along N (32 each)
    int m0 = blockIdx.y * 128, n0 = blockIdx.x * 128;

    uint32_t sA = (uint32_t)__cvta_generic_to_shared(AsF);
    uint32_t sB = (uint32_t)__cvta_generic_to_shared(BsF);

    // staging: row = tid>>1 (0..127), half-offset = (tid&1)*16, 2 x 16B
    int row = tid >> 1;
    int hc = (tid & 1) * 16;
    const __half* Ap = A + (long)(m0 + row) * lda + hc;
    const __half* Bp = Bm + (long)(n0 + row) * ldb + hc;
    uint32_t dstOff = (uint32_t)(row * STRIDE_W + (tid & 1) * 8) * 4u;

    float acc[4][4][4];
#pragma unroll
    for (int i = 0; i < 4; i++)
#pragma unroll
        for (int j = 0; j < 4; j++)
#pragma unroll
            for (int r = 0; r < 4; r++) acc[i][j][r] = 0.f;

    // ---- stage slab 0 into buffer 0 ----
    CP_ASYNC16(sA + dstOff,       Ap);
    CP_ASYNC16(sA + dstOff + 16u, Ap + 8);
    CP_ASYNC16(sB + dstOff,       Bp);
    CP_ASYNC16(sB + dstOff + 16u, Bp + 8);
    CP_COMMIT();
    CP_WAIT0();
    __syncthreads();

    const __half* ApNext = Ap + 32;
    const __half* BpNext = Bp + 32;
    int buf = 0;
    const uint32_t bufBytes = BUF_WORDS * 4u;

    for (int kt = 0; kt < K; kt += 32) {
        bool has_next = (kt + 32 < K);
        if (has_next) {
            uint32_t off = (buf ^ 1) ? bufBytes : 0u;
            CP_ASYNC16(sA + off + dstOff,       ApNext);
            CP_ASYNC16(sA + off + dstOff + 16u, ApNext + 8);
            CP_ASYNC16(sB + off + dstOff,       BpNext);
            CP_ASYNC16(sB + off + dstOff + 16u, BpNext + 8);
            CP_COMMIT();
            ApNext += 32;
            BpNext += 32;
        }

        const uint32_t* Ab = AsF + buf * BUF_WORDS;
        const uint32_t* Bb = BsF + buf * BUF_WORDS;
#pragma unroll
        for (int kk = 0; kk < 2; kk++) {          // two K=16 steps per slab
            int w0 = kk * 8;
            uint32_t af[4][4], bf[4][2];
#pragma unroll
            for (int im = 0; im < 4; im++) {
                int rowb = warp_m * 64 + im * 16 + g;
                af[im][0] = Ab[rowb * STRIDE_W + w0 + tg];
                af[im][1] = Ab[(rowb + 8) * STRIDE_W + w0 + tg];
                af[im][2] = Ab[rowb * STRIDE_W + w0 + tg + 4];
                af[im][3] = Ab[(rowb + 8) * STRIDE_W + w0 + tg + 4];
            }
#pragma unroll
            for (int jn = 0; jn < 4; jn++) {
                int colb = warp_n * 32 + jn * 8 + g;
                bf[jn][0] = Bb[colb * STRIDE_W + w0 + tg];
                bf[jn][1] = Bb[colb * STRIDE_W + w0 + tg + 4];
            }
#pragma unroll
            for (int im = 0; im < 4; im++)
#pragma unroll
                for (int jn = 0; jn < 4; jn++)
                    mma_f16(acc[im][jn], af[im], bf[jn]);
        }

        if (has_next) {
            CP_WAIT0();
            __syncthreads();
            buf ^= 1;
        }
    }

    // Epilogue: c0,c1 at (row g, cols 2tg,2tg+1), c2,c3 at row g+8
#pragma unroll
    for (int im = 0; im < 4; im++) {
#pragma unroll
        for (int jn = 0; jn < 4; jn++) {
            int r0 = m0 + warp_m * 64 + im * 16 + g;
            int c0 = n0 + warp_n * 32 + jn * 8 + tg * 2;
            float2 bb = make_float2(0.f, 0.f);
            if (bias) bb = *(const float2*)(bias + c0);
            float2 o0 = make_float2(acc[im][jn][0] + bb.x, acc[im][jn][1] + bb.y);
            float2 o1 = make_float2(acc[im][jn][2] + bb.x, acc[im][jn][3] + bb.y);
            if (OUTH) {
                __half* C = (__half*)Cv + coff;
                *(__half2*)(C + (long)r0 * ldc + c0) = __floats2half2_rn(o0.x, o0.y);
                *(__half2*)(C + (long)(r0 + 8) * ldc + c0) = __floats2half2_rn(o1.x, o1.y);
            } else {
                float* C = (float*)Cv + coff;
                if (resid) {
                    const float* R = resid + coff;
                    float2 rr0 = *(const float2*)(R + (long)r0 * ldc + c0);
                    float2 rr1 = *(const float2*)(R + (long)(r0 + 8) * ldc + c0);
                    o0.x += rr0.x; o0.y += rr0.y;
                    o1.x += rr1.x; o1.y += rr1.y;
                }
                *(float2*)(C + (long)r0 * ldc + c0) = o0;
                *(float2*)(C + (long)(r0 + 8) * ldc + c0) = o1;
            }
        }
    }
}

// ---------------- launcher -------------------------------------------------
extern "C" void kernel_launch(void* const* d_in, const int* in_sizes, int n_in,
                              void* d_out, int out_size) {
    (void)in_sizes; (void)n_in; (void)out_size;
    const float* hs        = (const float*)d_in[0];
    const float* mask      = (const float*)d_in[1];
    const float* q_w       = (const float*)d_in[2];
    const float* q_b       = (const float*)d_in[3];
    const float* k_w       = (const float*)d_in[4];
    const float* k_b       = (const float*)d_in[5];
    const float* v_w       = (const float*)d_in[6];
    const float* v_b       = (const float*)d_in[7];
    const float* o_w       = (const float*)d_in[8];
    const float* o_b       = (const float*)d_in[9];
    const float* fc1_w     = (const float*)d_in[10];
    const float* fc1_b     = (const float*)d_in[11];
    const float* fc2_w     = (const float*)d_in[12];
    const float* fc2_b     = (const float*)d_in[13];
    const float* in_norm_w = (const float*)d_in[14];
    const float* post_norm_w = (const float*)d_in[15];
    float* out = (float*)d_out;

    float *sc, *hid;
    __half *xnh, *qh, *kh, *vh, *vt, *p, *ctxh, *yh, *fc1h, *acth;
    __half *qwT, *kwT, *vwT, *owT, *fc1wT, *fc2wT;
    cudaGetSymbolAddress((void**)&sc,   g_scores);
    cudaGetSymbolAddress((void**)&hid,  g_hidden);
    cudaGetSymbolAddress((void**)&xnh,  g_xnh);
    cudaGetSymbolAddress((void**)&qh,   g_qh);
    cudaGetSymbolAddress((void**)&kh,   g_kh);
    cudaGetSymbolAddress((void**)&vh,   g_vh);
    cudaGetSymbolAddress((void**)&vt,   g_vt);
    cudaGetSymbolAddress((void**)&p,    g_p);
    cudaGetSymbolAddress((void**)&ctxh, g_ctxh);
    cudaGetSymbolAddress((void**)&yh,   g_yh);
    cudaGetSymbolAddress((void**)&fc1h, g_fc1h);
    cudaGetSymbolAddress((void**)&acth, g_acth);
    cudaGetSymbolAddress((void**)&qwT,  g_qwT);
    cudaGetSymbolAddress((void**)&kwT,  g_kwT);
    cudaGetSymbolAddress((void**)&vwT,  g_vwT);
    cudaGetSymbolAddress((void**)&owT,  g_owT);
    cudaGetSymbolAddress((void**)&fc1wT, g_fc1wT);
    cudaGetSymbolAddress((void**)&fc2wT, g_fc2wT);

    dim3 tb(32, 8);
    // 0. weight transpose+cvt to fp16 [N][K]
    wt_kernel<<<dim3(Hv / 32, Hv / 32), tb>>>(q_w, qwT, Hv, Hv);
    wt_kernel<<<dim3(Hv / 32, Hv / 32), tb>>>(k_w, kwT, Hv, Hv);
    wt_kernel<<<dim3(Hv / 32, Hv / 32), tb>>>(v_w, vwT, Hv, Hv);
    wt_kernel<<<dim3(Hv / 32, Hv / 32), tb>>>(o_w, owT, Hv, Hv);
    wt_kernel<<<dim3(2 * Iv / 32, Hv / 32), tb>>>(fc1_w, fc1wT, Hv, 2 * Iv);
    wt_kernel<<<dim3(Hv / 32, Iv / 32), tb>>>(fc2_w, fc2wT, Iv, Hv);

    // 1. input RMSNorm -> fp16
    rmsnorm_kernel<<<Tv, 256>>>(hs, in_norm_w, xnh);

    // 2. Q/K/V projections -> fp16
    dim3 gProj(Hv / 128, Tv / 128, 1);
    hgemm_kernel<true><<<gProj, 256>>>(xnh, qwT, q_b, nullptr, qh,
        Tv, Hv, Hv, Hv, Hv, Hv, 1, 0, 0, 0, 0, 0, 0);
    hgemm_kernel<true><<<gProj, 256>>>(xnh, kwT, k_b, nullptr, kh,
        Tv, Hv, Hv, Hv, Hv, Hv, 1, 0, 0, 0, 0, 0, 0);
    hgemm_kernel<true><<<gProj, 256>>>(xnh, vwT, v_b, nullptr, vh,
        Tv, Hv, Hv, Hv, Hv, Hv, 1, 0, 0, 0, 0, 0, 0);

    // 3. V per-head transpose -> [bh][hd][s]
    vtr_kernel<<<dim3(Sv / 32, HDv / 32, Bv * NHv), tb>>>(vh, vt);

    // 4. scores = Q @ K^T (fp32 out), batched over 32 heads
    dim3 gSc(Sv / 128, Sv / 128, Bv * NHv);
    hgemm_kernel<false><<<gSc, 256>>>(qh, kh, nullptr, nullptr, sc,
        Sv, Sv, HDv, Hv, Hv, Sv, NHv,
        HDv, (long)Sv * Hv, HDv, (long)Sv * Hv,
        (long)Sv * Sv, (long)NHv * Sv * Sv);

    // 5. softmax -> fp16 probs
    softmax_kernel<<<Bv * NHv * Sv, 256>>>(sc, mask, p);

    // 6. ctx = P @ V  (B = vt [hd][s], TRANSB-form) -> fp16
    dim3 gCtx(HDv / 128, Sv / 128, Bv * NHv);
    hgemm_kernel<true><<<gCtx, 256>>>(p, vt, nullptr, nullptr, ctxh,
        Sv, HDv, Sv, Sv, Sv, Hv, NHv,
        (long)Sv * Sv, (long)NHv * Sv * Sv,
        (long)HDv * Sv, (long)NHv * HDv * Sv,
        HDv, (long)Sv * Hv);

    // 7. O projection + residual -> hidden (fp32)
    hgemm_kernel<false><<<gProj, 256>>>(ctxh, owT, o_b, hs, hid,
        Tv, Hv, Hv, Hv, Hv, Hv, 1, 0, 0, 0, 0, 0, 0);

    // 8. post RMSNorm -> fp16
    rmsnorm_kernel<<<Tv, 256>>>(hid, post_norm_w, yh);

    // 9. FC1 -> fp16
    dim3 gFc1((2 * Iv) / 128, Tv / 128, 1);
    hgemm_kernel<true><<<gFc1, 256>>>(yh, fc1wT, fc1_b, nullptr, fc1h,
        Tv, 2 * Iv, Hv, Hv, Hv, 2 * Iv, 1, 0, 0, 0, 0, 0, 0);

    // 10. SwiGLU -> fp16
    swiglu_kernel<<<(Tv * Iv / 8 + 255) / 256, 256>>>(fc1h, acth);

    // 11. FC2 + residual -> out (fp32)
    hgemm_kernel<false><<<gProj, 256>>>(acth, fc2wT, fc2_b, hid, out,
        Tv, Hv, Iv, Iv, Iv, Hv, 1, 0, 0, 0, 0, 0, 0);
}

// round 17
// speedup vs baseline: 2.1539x; 1.0699x over previous
#include <cuda_runtime.h>
#include <cuda_fp16.h>
#include <math.h>
#include <stdint.h>

// Problem constants
#define Bv   2
#define Sv   2048
#define Hv   2048
#define NHv  16
#define HDv  128
#define Iv   5632
#define Tv   (Bv * Sv)            // 4096 tokens
#define EPSv 1e-5f
#define SCALEv 0.08838834764831845f   // 1/sqrt(128)

// hgemm smem geometry (validated R16): row stride 20 words (20 mod 32) ->
// fragment bank (20g+tg) mod 32 bijection -> conflict-free.
#define STRIDE_W 20
#define BUF_WORDS (128 * STRIDE_W)   // 2560 words = 10 KB per buffer

// Flash-attention smem geometry: row = 128 halves = 64 words, stride 68
// (68 mod 32 = 4) -> fragment bank (4g+tg) bijection -> conflict-free.
#define FA_STRIDE 68
#define FA_TILE_W (128 * FA_STRIDE)          // 8704 words per tile
#define FA_Q_OFF   0
#define FA_K_OFF   FA_TILE_W                 // 2 buffers
#define FA_V_OFF   (3 * FA_TILE_W)           // 2 buffers
#define FA_MADS_OFF (5 * FA_TILE_W)          // 2 x 128 floats
#define FA_WORDS   (5 * FA_TILE_W + 256)
#define FA_SMEM_BYTES (FA_WORDS * 4)         // 175,104 B

// ---------------- scratch (static __device__: allocation-free) -------------
__device__ float  g_hidden[Tv * Hv];
__device__ __half g_xnh[Tv * Hv];
__device__ __half g_qh[Tv * Hv];
__device__ __half g_kh[Tv * Hv];
__device__ __half g_vh[Tv * Hv];
__device__ __half g_vt[Tv * Hv];          // per-head transposed V [bh][hd][s]
__device__ __half g_ctxh[Tv * Hv];
__device__ __half g_yh[Tv * Hv];
__device__ __half g_fc1h[(size_t)Tv * 2 * Iv];
__device__ __half g_acth[(size_t)Tv * Iv];
// fp16 transposed weights [N][K]
__device__ __half g_qwT[Hv * Hv];
__device__ __half g_kwT[Hv * Hv];
__device__ __half g_vwT[Hv * Hv];
__device__ __half g_owT[Hv * Hv];
__device__ __half g_fc1wT[(size_t)2 * Iv * Hv];
__device__ __half g_fc2wT[(size_t)Hv * Iv];

// ---------------- mma + cp.async helpers ----------------------------------
__device__ __forceinline__ void mma_f16(float* d, const uint32_t* a, const uint32_t* b) {
    asm volatile(
        "mma.sync.aligned.m16n8k16.row.col.f32.f16.f16.f32 "
        "{%0,%1,%2,%3}, {%4,%5,%6,%7}, {%8,%9}, {%0,%1,%2,%3};\n"
        : "+f"(d[0]), "+f"(d[1]), "+f"(d[2]), "+f"(d[3])
        : "r"(a[0]), "r"(a[1]), "r"(a[2]), "r"(a[3]), "r"(b[0]), "r"(b[1]));
}

#define CP_ASYNC16(dst_u32, src_ptr) \
    asm volatile("cp.async.cg.shared.global [%0], [%1], 16;" :: "r"(dst_u32), "l"(src_ptr))
#define CP_COMMIT() asm volatile("cp.async.commit_group;" ::: "memory")
#define CP_WAIT0()  asm volatile("cp.async.wait_group 0;" ::: "memory")

// ---------------- weight transpose+cvt: fp32 [K][N] -> fp16 [N][K] --------
__global__ void wt_kernel(const float* __restrict__ in, __half* __restrict__ out,
                          int K, int N) {
    __shared__ __half tile[32][33];
    int nb = blockIdx.x * 32, kb = blockIdx.y * 32;
    int tx = threadIdx.x, ty = threadIdx.y;   // 32 x 8
#pragma unroll
    for (int i = 0; i < 4; i++) {
        int r = ty + 8 * i;
        tile[r][tx] = __float2half_rn(in[(size_t)(kb + r) * N + nb + tx]);
    }
    __syncthreads();
#pragma unroll
    for (int i = 0; i < 4; i++) {
        int r = ty + 8 * i;
        out[(size_t)(nb + r) * K + kb + tx] = tile[tx][r];
    }
}

// ---------------- V transpose: [b,s,h,d] fp16 -> [bh][d][s] fp16 ----------
__global__ void vtr_kernel(const __half* __restrict__ vh, __half* __restrict__ vt) {
    __shared__ __half tile[32][33];
    int z = blockIdx.z;
    int b = z / NHv, h = z % NHv;
    int sb = blockIdx.x * 32, db = blockIdx.y * 32;
    int tx = threadIdx.x, ty = threadIdx.y;
#pragma unroll
    for (int i = 0; i < 4; i++) {
        int r = ty + 8 * i;
        tile[r][tx] = vh[(size_t)(b * Sv + sb + r) * Hv + h * HDv + db + tx];
    }
    __syncthreads();
#pragma unroll
    for (int i = 0; i < 4; i++) {
        int r = ty + 8 * i;
        vt[((size_t)z * HDv + db + r) * Sv + sb + tx] = tile[tx][r];
    }
}

// ---------------- RMSNorm: fp32 in -> fp16 out ----------------------------
__global__ void rmsnorm_kernel(const float* __restrict__ x,
                               const float* __restrict__ w,
                               __half* __restrict__ out) {
    int r = blockIdx.x;
    const float* xr = x + (size_t)r * Hv;
    __half* orow = out + (size_t)r * Hv;
    float v[8];
    float ss = 0.f;
#pragma unroll
    for (int i = 0; i < 8; i++) {
        v[i] = xr[threadIdx.x + i * 256];
        ss += v[i] * v[i];
    }
    __shared__ float red[32];
    int lane = threadIdx.x & 31, wid = threadIdx.x >> 5;
#pragma unroll
    for (int o = 16; o > 0; o >>= 1) ss += __shfl_xor_sync(0xffffffffu, ss, o);
    if (lane == 0) red[wid] = ss;
    __syncthreads();
    if (wid == 0) {
        float t = (lane < 8) ? red[lane] : 0.f;
#pragma unroll
        for (int o = 4; o > 0; o >>= 1) t += __shfl_xor_sync(0xffffffffu, t, o);
        if (lane == 0) red[0] = rsqrtf(t * (1.0f / Hv) + EPSv);
    }
    __syncthreads();
    float rs = red[0];
#pragma unroll
    for (int i = 0; i < 8; i++) {
        int c = threadIdx.x + i * 256;
        orow[c] = __float2half_rn(v[i] * rs * w[c]);
    }
}

// ---------------- SwiGLU: fp16 in/out, fp32 math --------------------------
__global__ void swiglu_kernel(const __half* __restrict__ h,
                              __half* __restrict__ act) {
    int idx = blockIdx.x * blockDim.x + threadIdx.x;   // 8-half units
    int total8 = Tv * Iv / 8;
    if (idx >= total8) return;
    int per8 = Iv / 8;
    int t = idx / per8, j = idx - t * per8;
    const __half* base = h + (size_t)t * (2 * Iv) + j * 8;
    uint4 gv = *(const uint4*)(base);
    uint4 uv = *(const uint4*)(base + Iv);
    const __half2* g2 = (const __half2*)&gv;
    const __half2* u2 = (const __half2*)&uv;
    uint4 ov;
    __half2* o2 = (__half2*)&ov;
#pragma unroll
    for (int i = 0; i < 4; i++) {
        float2 gf = __half22float2(g2[i]);
        float2 uf = __half22float2(u2[i]);
        float r0 = (gf.x / (1.0f + __expf(-gf.x))) * uf.x;
        float r1 = (gf.y / (1.0f + __expf(-gf.y))) * uf.y;
        o2[i] = __floats2half2_rn(r0, r1);
    }
    *(uint4*)(act + (size_t)t * Iv + j * 8) = ov;
}

// ---------------- Flash attention ------------------------------------------
// Grid (Sv/128, Bv*NHv), 256 threads. Per CTA: Q-tile 128 rows of one head;
// loop 16 K/V tiles (double-buffered cp.async). Warp w owns rows
// [16w,16w+16) x full 128 cols -> P fragments stay in-register for ctx MMA.
__global__ __launch_bounds__(256)
void fa_kernel(const __half* __restrict__ qh, const __half* __restrict__ kh,
               const __half* __restrict__ vt, const float* __restrict__ mask,
               __half* __restrict__ ctxh) {
    extern __shared__ uint32_t fsm[];
    uint32_t* Qs = fsm + FA_Q_OFF;
    float* mads = (float*)(fsm + FA_MADS_OFF);

    int tid = threadIdx.x;
    int lane = tid & 31;
    int warp = tid >> 5;
    int g = lane >> 2;
    int tg = lane & 3;
    int wm16 = warp * 16;

    int bh = blockIdx.y;
    int b = bh / NHv, h = bh % NHv;
    int q0 = blockIdx.x * 128;

    uint32_t sBase = (uint32_t)__cvta_generic_to_shared(fsm);

    // staging: 2 threads per row, each 8 x 16B (128 halves per row)
    int r = tid >> 1;
    int hs = tid & 1;                 // half-row selector
    uint32_t dRow = (uint32_t)(r * FA_STRIDE + hs * 32) * 4u;
    const __half* qsrc = qh + (size_t)(b * Sv + q0 + r) * Hv + h * HDv + hs * 64;
    const __half* ksrc0 = kh + (size_t)(b * Sv + r) * Hv + h * HDv + hs * 64;
    const __half* vsrc0 = vt + (size_t)(bh * HDv + r) * Sv + hs * 64;

    // prologue: Q + K0 + V0
#pragma unroll
    for (int i = 0; i < 8; i++)
        CP_ASYNC16(sBase + (FA_Q_OFF * 4u) + dRow + i * 16u, qsrc + i * 8);
#pragma unroll
    for (int i = 0; i < 8; i++)
        CP_ASYNC16(sBase + (FA_K_OFF * 4u) + dRow + i * 16u, ksrc0 + i * 8);
#pragma unroll
    for (int i = 0; i < 8; i++)
        CP_ASYNC16(sBase + (FA_V_OFF * 4u) + dRow + i * 16u, vsrc0 + i * 8);
    CP_COMMIT();
    if (tid < 128)
        mads[tid] = (1.0f - mask[(size_t)b * Sv + tid]) * -10000.0f;
    CP_WAIT0();
    __syncthreads();

    float m0 = -1e30f, m1 = -1e30f, l0 = 0.f, l1 = 0.f;
    float cacc[16][4];
#pragma unroll
    for (int jd = 0; jd < 16; jd++)
#pragma unroll
        for (int rr = 0; rr < 4; rr++) cacc[jd][rr] = 0.f;

    int buf = 0;
    for (int j = 0; j < 16; j++) {
        if (j < 15) {
            int nb = buf ^ 1;
            const __half* ksrc = kh + (size_t)(b * Sv + (j + 1) * 128 + r) * Hv + h * HDv + hs * 64;
            const __half* vsrc = vt + (size_t)(bh * HDv + r) * Sv + (j + 1) * 128 + hs * 64;
            uint32_t kOff = (FA_K_OFF + nb * FA_TILE_W) * 4u;
            uint32_t vOff = (FA_V_OFF + nb * FA_TILE_W) * 4u;
#pragma unroll
            for (int i = 0; i < 8; i++)
                CP_ASYNC16(sBase + kOff + dRow + i * 16u, ksrc + i * 8);
#pragma unroll
            for (int i = 0; i < 8; i++)
                CP_ASYNC16(sBase + vOff + dRow + i * 16u, vsrc + i * 8);
            CP_COMMIT();
            if (tid < 128)
                mads[nb * 128 + tid] =
                    (1.0f - mask[(size_t)b * Sv + (j + 1) * 128 + tid]) * -10000.0f;
        }

        const uint32_t* Kb = fsm + FA_K_OFF + buf * FA_TILE_W;
        const uint32_t* Vb = fsm + FA_V_OFF + buf * FA_TILE_W;
        const float* md = mads + buf * 128;

        // ---- scores: S = Q @ K^T  (16 x 128 per warp) ----
        float sacc[16][4];
#pragma unroll
        for (int jn = 0; jn < 16; jn++)
#pragma unroll
            for (int rr = 0; rr < 4; rr++) sacc[jn][rr] = 0.f;
#pragma unroll
        for (int ks = 0; ks < 8; ks++) {
            uint32_t aq[4];
            int rowb = wm16 + g;
            aq[0] = Qs[rowb * FA_STRIDE + ks * 8 + tg];
            aq[1] = Qs[(rowb + 8) * FA_STRIDE + ks * 8 + tg];
            aq[2] = Qs[rowb * FA_STRIDE + ks * 8 + tg + 4];
            aq[3] = Qs[(rowb + 8) * FA_STRIDE + ks * 8 + tg + 4];
#pragma unroll
            for (int jn = 0; jn < 16; jn++) {
                uint32_t bb[2];
                bb[0] = Kb[(jn * 8 + g) * FA_STRIDE + ks * 8 + tg];
                bb[1] = Kb[(jn * 8 + g) * FA_STRIDE + ks * 8 + tg + 4];
                mma_f16(sacc[jn], aq, bb);
            }
        }

        // ---- online softmax (rows g and g+8) ----
        float mx0 = -1e30f, mx1 = -1e30f;
#pragma unroll
        for (int jn = 0; jn < 16; jn++) {
            float ma = md[jn * 8 + 2 * tg], mb2 = md[jn * 8 + 2 * tg + 1];
            sacc[jn][0] = sacc[jn][0] * SCALEv + ma;
            sacc[jn][1] = sacc[jn][1] * SCALEv + mb2;
            sacc[jn][2] = sacc[jn][2] * SCALEv + ma;
            sacc[jn][3] = sacc[jn][3] * SCALEv + mb2;
            mx0 = fmaxf(mx0, fmaxf(sacc[jn][0], sacc[jn][1]));
            mx1 = fmaxf(mx1, fmaxf(sacc[jn][2], sacc[jn][3]));
        }
        mx0 = fmaxf(mx0, __shfl_xor_sync(0xffffffffu, mx0, 1));
        mx0 = fmaxf(mx0, __shfl_xor_sync(0xffffffffu, mx0, 2));
        mx1 = fmaxf(mx1, __shfl_xor_sync(0xffffffffu, mx1, 1));
        mx1 = fmaxf(mx1, __shfl_xor_sync(0xffffffffu, mx1, 2));
        float mn0 = fmaxf(m0, mx0), mn1 = fmaxf(m1, mx1);
        float sc0 = __expf(m0 - mn0), sc1 = __expf(m1 - mn1);
        m0 = mn0; m1 = mn1;

        float sum0 = 0.f, sum1 = 0.f;
#pragma unroll
        for (int jn = 0; jn < 16; jn++) {
            sacc[jn][0] = __expf(sacc[jn][0] - m0);
            sacc[jn][1] = __expf(sacc[jn][1] - m0);
            sacc[jn][2] = __expf(sacc[jn][2] - m1);
            sacc[jn][3] = __expf(sacc[jn][3] - m1);
            sum0 += sacc[jn][0] + sacc[jn][1];
            sum1 += sacc[jn][2] + sacc[jn][3];
        }
        sum0 += __shfl_xor_sync(0xffffffffu, sum0, 1);
        sum0 += __shfl_xor_sync(0xffffffffu, sum0, 2);
        sum1 += __shfl_xor_sync(0xffffffffu, sum1, 1);
        sum1 += __shfl_xor_sync(0xffffffffu, sum1, 2);
        l0 = l0 * sc0 + sum0;
        l1 = l1 * sc1 + sum1;

        // rescale ctx acc
#pragma unroll
        for (int jd = 0; jd < 16; jd++) {
            cacc[jd][0] *= sc0; cacc[jd][1] *= sc0;
            cacc[jd][2] *= sc1; cacc[jd][3] *= sc1;
        }

        // pack P to fp16 A-fragments (C layout -> A layout, warp-local)
        uint32_t pf[8][4];
#pragma unroll
        for (int kc = 0; kc < 8; kc++) {
            __half2 h0 = __floats2half2_rn(sacc[2 * kc][0], sacc[2 * kc][1]);
            __half2 h1 = __floats2half2_rn(sacc[2 * kc][2], sacc[2 * kc][3]);
            __half2 h2 = __floats2half2_rn(sacc[2 * kc + 1][0], sacc[2 * kc + 1][1]);
            __half2 h3 = __floats2half2_rn(sacc[2 * kc + 1][2], sacc[2 * kc + 1][3]);
            pf[kc][0] = *(uint32_t*)&h0;
            pf[kc][1] = *(uint32_t*)&h1;
            pf[kc][2] = *(uint32_t*)&h2;
            pf[kc][3] = *(uint32_t*)&h3;
        }

        // ---- ctx += P @ V^T (V tile rows = d, cols = s) ----
#pragma unroll
        for (int kc = 0; kc < 8; kc++) {
#pragma unroll
            for (int jd = 0; jd < 16; jd++) {
                uint32_t bb[2];
                bb[0] = Vb[(jd * 8 + g) * FA_STRIDE + kc * 8 + tg];
                bb[1] = Vb[(jd * 8 + g) * FA_STRIDE + kc * 8 + tg + 4];
                mma_f16(cacc[jd], pf[kc], bb);
            }
        }

        if (j < 15) {
            CP_WAIT0();
            __syncthreads();
            buf ^= 1;
        }
    }

    // epilogue: normalize and store fp16 ctx
    float inv0 = 1.0f / l0, inv1 = 1.0f / l1;
    long rowg = (long)(b * Sv + q0 + wm16 + g) * Hv + h * HDv;
#pragma unroll
    for (int jd = 0; jd < 16; jd++) {
        int c0 = jd * 8 + 2 * tg;
        *(__half2*)(ctxh + rowg + c0) =
            __floats2half2_rn(cacc[jd][0] * inv0, cacc[jd][1] * inv0);
        *(__half2*)(ctxh + rowg + 8 * Hv + c0) =
            __floats2half2_rn(cacc[jd][2] * inv1, cacc[jd][3] * inv1);
    }
}

// ---------------- fp16 tensor-core GEMM: C = A @ B^T [+bias] [+resid] -----
template <bool OUTH>
__global__ __launch_bounds__(256, 2)
void hgemm_kernel(const __half* __restrict__ A, const __half* __restrict__ Bm,
                  const float* __restrict__ bias, const float* __restrict__ resid,
                  void* __restrict__ Cv,
                  int M, int N, int K, int lda, int ldb, int ldc,
                  int bInner,
                  long aIn, long aOut, long bIn, long bOut, long cIn, long cOut) {
    int z = blockIdx.z;
    int zi = z % bInner, zo = z / bInner;
    A += (long)zi * aIn + (long)zo * aOut;
    Bm += (long)zi * bIn + (long)zo * bOut;
    long coff = (long)zi * cIn + (long)zo * cOut;

    __shared__ uint32_t AsF[2 * BUF_WORDS];
    __shared__ uint32_t BsF[2 * BUF_WORDS];

    int tid = threadIdx.x;
    int lane = tid & 31;
    int warp = tid >> 5;
    int g = lane >> 2;
    int tg = lane & 3;
    int warp_m = warp & 1;
    int warp_n = warp >> 1;
    int m0 = blockIdx.y * 128, n0 = blockIdx.x * 128;

    uint32_t sA = (uint32_t)__cvta_generic_to_shared(AsF);
    uint32_t sB = (uint32_t)__cvta_generic_to_shared(BsF);

    int row = tid >> 1;
    int hc = (tid & 1) * 16;
    const __half* Ap = A + (long)(m0 + row) * lda + hc;
    const __half* Bp = Bm + (long)(n0 + row) * ldb + hc;
    uint32_t dstOff = (uint32_t)(row * STRIDE_W + (tid & 1) * 8) * 4u;

    float acc[4][4][4];
#pragma unroll
    for (int i = 0; i < 4; i++)
#pragma unroll
        for (int j = 0; j < 4; j++)
#pragma unroll
            for (int r = 0; r < 4; r++) acc[i][j][r] = 0.f;

    CP_ASYNC16(sA + dstOff,       Ap);
    CP_ASYNC16(sA + dstOff + 16u, Ap + 8);
    CP_ASYNC16(sB + dstOff,       Bp);
    CP_ASYNC16(sB + dstOff + 16u, Bp + 8);
    CP_COMMIT();
    CP_WAIT0();
    __syncthreads();

    const __half* ApNext = Ap + 32;
    const __half* BpNext = Bp + 32;
    int buf = 0;
    const uint32_t bufBytes = BUF_WORDS * 4u;

    for (int kt = 0; kt < K; kt += 32) {
        bool has_next = (kt + 32 < K);
        if (has_next) {
            uint32_t off = (buf ^ 1) ? bufBytes : 0u;
            CP_ASYNC16(sA + off + dstOff,       ApNext);
            CP_ASYNC16(sA + off + dstOff + 16u, ApNext + 8);
            CP_ASYNC16(sB + off + dstOff,       BpNext);
            CP_ASYNC16(sB + off + dstOff + 16u, BpNext + 8);
            CP_COMMIT();
            ApNext += 32;
            BpNext += 32;
        }

        const uint32_t* Ab = AsF + buf * BUF_WORDS;
        const uint32_t* Bb = BsF + buf * BUF_WORDS;
#pragma unroll
        for (int kk = 0; kk < 2; kk++) {
            int w0 = kk * 8;
            uint32_t af[4][4], bf[4][2];
#pragma unroll
            for (int im = 0; im < 4; im++) {
                int rowb = warp_m * 64 + im * 16 + g;
                af[im][0] = Ab[rowb * STRIDE_W + w0 + tg];
                af[im][1] = Ab[(rowb + 8) * STRIDE_W + w0 + tg];
                af[im][2] = Ab[rowb * STRIDE_W + w0 + tg + 4];
                af[im][3] = Ab[(rowb + 8) * STRIDE_W + w0 + tg + 4];
            }
#pragma unroll
            for (int jn = 0; jn < 4; jn++) {
                int colb = warp_n * 32 + jn * 8 + g;
                bf[jn][0] = Bb[colb * STRIDE_W + w0 + tg];
                bf[jn][1] = Bb[colb * STRIDE_W + w0 + tg + 4];
            }
#pragma unroll
            for (int im = 0; im < 4; im++)
#pragma unroll
                for (int jn = 0; jn < 4; jn++)
                    mma_f16(acc[im][jn], af[im], bf[jn]);
        }

        if (has_next) {
            CP_WAIT0();
            __syncthreads();
            buf ^= 1;
        }
    }

#pragma unroll
    for (int im = 0; im < 4; im++) {
#pragma unroll
        for (int jn = 0; jn < 4; jn++) {
            int r0 = m0 + warp_m * 64 + im * 16 + g;
            int c0 = n0 + warp_n * 32 + jn * 8 + tg * 2;
            float2 bb = make_float2(0.f, 0.f);
            if (bias) bb = *(const float2*)(bias + c0);
            float2 o0 = make_float2(acc[im][jn][0] + bb.x, acc[im][jn][1] + bb.y);
            float2 o1 = make_float2(acc[im][jn][2] + bb.x, acc[im][jn][3] + bb.y);
            if (OUTH) {
                __half* C = (__half*)Cv + coff;
                *(__half2*)(C + (long)r0 * ldc + c0) = __floats2half2_rn(o0.x, o0.y);
                *(__half2*)(C + (long)(r0 + 8) * ldc + c0) = __floats2half2_rn(o1.x, o1.y);
            } else {
                float* C = (float*)Cv + coff;
                if (resid) {
                    const float* R = resid + coff;
                    float2 rr0 = *(const float2*)(R + (long)r0 * ldc + c0);
                    float2 rr1 = *(const float2*)(R + (long)(r0 + 8) * ldc + c0);
                    o0.x += rr0.x; o0.y += rr0.y;
                    o1.x += rr1.x; o1.y += rr1.y;
                }
                *(float2*)(C + (long)r0 * ldc + c0) = o0;
                *(float2*)(C + (long)(r0 + 8) * ldc + c0) = o1;
            }
        }
    }
}

// ---------------- launcher -------------------------------------------------
extern "C" void kernel_launch(void* const* d_in, const int* in_sizes, int n_in,
                              void* d_out, int out_size) {
    (void)in_sizes; (void)n_in; (void)out_size;
    const float* hs        = (const float*)d_in[0];
    const float* mask      = (const float*)d_in[1];
    const float* q_w       = (const float*)d_in[2];
    const float* q_b       = (const float*)d_in[3];
    const float* k_w       = (const float*)d_in[4];
    const float* k_b       = (const float*)d_in[5];
    const float* v_w       = (const float*)d_in[6];
    const float* v_b       = (const float*)d_in[7];
    const float* o_w       = (const float*)d_in[8];
    const float* o_b       = (const float*)d_in[9];
    const float* fc1_w     = (const float*)d_in[10];
    const float* fc1_b     = (const float*)d_in[11];
    const float* fc2_w     = (const float*)d_in[12];
    const float* fc2_b     = (const float*)d_in[13];
    const float* in_norm_w = (const float*)d_in[14];
    const float* post_norm_w = (const float*)d_in[15];
    float* out = (float*)d_out;

    float *hid;
    __half *xnh, *qh, *kh, *vh, *vt, *ctxh, *yh, *fc1h, *acth;
    __half *qwT, *kwT, *vwT, *owT, *fc1wT, *fc2wT;
    cudaGetSymbolAddress((void**)&hid,  g_hidden);
    cudaGetSymbolAddress((void**)&xnh,  g_xnh);
    cudaGetSymbolAddress((void**)&qh,   g_qh);
    cudaGetSymbolAddress((void**)&kh,   g_kh);
    cudaGetSymbolAddress((void**)&vh,   g_vh);
    cudaGetSymbolAddress((void**)&vt,   g_vt);
    cudaGetSymbolAddress((void**)&ctxh, g_ctxh);
    cudaGetSymbolAddress((void**)&yh,   g_yh);
    cudaGetSymbolAddress((void**)&fc1h, g_fc1h);
    cudaGetSymbolAddress((void**)&acth, g_acth);
    cudaGetSymbolAddress((void**)&qwT,  g_qwT);
    cudaGetSymbolAddress((void**)&kwT,  g_kwT);
    cudaGetSymbolAddress((void**)&vwT,  g_vwT);
    cudaGetSymbolAddress((void**)&owT,  g_owT);
    cudaGetSymbolAddress((void**)&fc1wT, g_fc1wT);
    cudaGetSymbolAddress((void**)&fc2wT, g_fc2wT);

    cudaFuncSetAttribute(fa_kernel,
                         cudaFuncAttributeMaxDynamicSharedMemorySize, FA_SMEM_BYTES);

    dim3 tb(32, 8);
    // 0. weight transpose+cvt to fp16 [N][K]
    wt_kernel<<<dim3(Hv / 32, Hv / 32), tb>>>(q_w, qwT, Hv, Hv);
    wt_kernel<<<dim3(Hv / 32, Hv / 32), tb>>>(k_w, kwT, Hv, Hv);
    wt_kernel<<<dim3(Hv / 32, Hv / 32), tb>>>(v_w, vwT, Hv, Hv);
    wt_kernel<<<dim3(Hv / 32, Hv / 32), tb>>>(o_w, owT, Hv, Hv);
    wt_kernel<<<dim3(2 * Iv / 32, Hv / 32), tb>>>(fc1_w, fc1wT, Hv, 2 * Iv);
    wt_kernel<<<dim3(Hv / 32, Iv / 32), tb>>>(fc2_w, fc2wT, Iv, Hv);

    // 1. input RMSNorm -> fp16
    rmsnorm_kernel<<<Tv, 256>>>(hs, in_norm_w, xnh);

    // 2. Q/K/V projections -> fp16
    dim3 gProj(Hv / 128, Tv / 128, 1);
    hgemm_kernel<true><<<gProj, 256>>>(xnh, qwT, q_b, nullptr, qh,
        Tv, Hv, Hv, Hv, Hv, Hv, 1, 0, 0, 0, 0, 0, 0);
    hgemm_kernel<true><<<gProj, 256>>>(xnh, kwT, k_b, nullptr, kh,
        Tv, Hv, Hv, Hv, Hv, Hv, 1, 0, 0, 0, 0, 0, 0);
    hgemm_kernel<true><<<gProj, 256>>>(xnh, vwT, v_b, nullptr, vh,
        Tv, Hv, Hv, Hv, Hv, Hv, 1, 0, 0, 0, 0, 0, 0);

    // 3. V per-head transpose -> [bh][hd][s]
    vtr_kernel<<<dim3(Sv / 32, HDv / 32, Bv * NHv), tb>>>(vh, vt);

    // 4. fused flash attention -> ctx fp16
    fa_kernel<<<dim3(Sv / 128, Bv * NHv), 256, FA_SMEM_BYTES>>>(qh, kh, vt, mask, ctxh);

    // 5. O projection + residual -> hidden (fp32)
    hgemm_kernel<false><<<gProj, 256>>>(ctxh, owT, o_b, hs, hid,
        Tv, Hv, Hv, Hv, Hv, Hv, 1, 0, 0, 0, 0, 0, 0);

    // 6. post RMSNorm -> fp16
    rmsnorm_kernel<<<Tv, 256>>>(hid, post_norm_w, yh);

    // 7. FC1 -> fp16
    dim3 gFc1((2 * Iv) / 128, Tv / 128, 1);
    hgemm_kernel<true><<<gFc1, 256>>>(yh, fc1wT, fc1_b, nullptr, fc1h,
        Tv, 2 * Iv, Hv, Hv, Hv, 2 * Iv, 1, 0, 0, 0, 0, 0, 0);

    // 8. SwiGLU -> fp16
    swiglu_kernel<<<(Tv * Iv / 8 + 255) / 256, 256>>>(fc1h, acth);

    // 9. FC2 + residual -> out (fp32)
    hgemm_kernel<false><<<gProj, 256>>>(acth, fc2wT, fc2_b, hid, out,
        Tv, Hv, Iv, Iv, Iv, Hv, 1, 0, 0, 0, 0, 0, 0);
}